// round 4
// baseline (speedup 1.0000x reference)
#include <cuda_runtime.h>
#include <math.h>

#define NN  100000
#define NE  6400000
#define IND 128

// ---------------- static device scratch (no runtime allocation) ----------------
static __device__ __align__(16) float g_deg[NN];
static __device__ __align__(16) float g_dis[NN];
static __device__ __align__(16) int   g_src[NE];
static __device__ __align__(16) int   g_dst[NE];
static __device__ __align__(16) float g_h[NN * 12];     // pre-scaled features h' = dis * (x @ W)
static __device__ __align__(16) float g_accA[NN * 12];  // ping accumulator
static __device__ __align__(16) float g_accB[NN * 12];  // pong accumulator
static __device__ int g_is64;

// ---------------- atomic reduction helpers (no return -> RED) ----------------
__device__ __forceinline__ void red1(float* p, float a) {
    asm volatile("red.global.add.f32 [%0], %1;" :: "l"(p), "f"(a) : "memory");
}
__device__ __forceinline__ void red2(float* p, float a, float b) {
    asm volatile("red.global.add.v2.f32 [%0], {%1, %2};" :: "l"(p), "f"(a), "f"(b) : "memory");
}
__device__ __forceinline__ void red4(float* p, float a, float b, float c, float d) {
    asm volatile("red.global.add.v4.f32 [%0], {%1, %2, %3, %4};"
                 :: "l"(p), "f"(a), "f"(b), "f"(c), "f"(d) : "memory");
}

// ---------------- dtype detection: int64 edge_index has zero high words ----------------
__global__ void k_detect(const unsigned int* __restrict__ p) {
    if (threadIdx.x == 0 && blockIdx.x == 0) {
        int is64 = 1;
        #pragma unroll
        for (int j = 0; j < 16; j++)
            if (p[2 * j + 1] != 0u) is64 = 0;
        g_is64 = is64;
    }
}

__global__ void k_init_deg(int n) {
    int i = blockIdx.x * blockDim.x + threadIdx.x;
    if (i < n) g_deg[i] = 1.0f;  // self-loop weight
}

// convert indices to int32 + accumulate weighted in-degree (over dst/col)
__global__ void k_deg_convert(const void* __restrict__ eiv, const float* __restrict__ ew, int E) {
    int e = blockIdx.x * blockDim.x + threadIdx.x;
    if (e >= E) return;
    int s, d;
    if (g_is64) {
        const long long* ei = (const long long*)eiv;
        s = (int)ei[e];
        d = (int)ei[(long long)E + e];
    } else {
        const int* ei = (const int*)eiv;
        s = ei[e];
        d = ei[E + e];
    }
    g_src[e] = s;
    g_dst[e] = d;
    red1(&g_deg[d], ew[e]);
}

__global__ void k_dis(int n) {
    int i = blockIdx.x * blockDim.x + threadIdx.x;
    if (i < n) g_dis[i] = rsqrtf(g_deg[i]);  // deg >= 1 always
}

// ---------------- layer 1 matmul: h' = dis * (X @ W1); accA init = h' (self loop) ----------------
__global__ void __launch_bounds__(128) k_mm1(const float* __restrict__ X,
                                             const float* __restrict__ W1, int n) {
    __shared__ float sW[IND * 12];
    for (int i = threadIdx.x; i < IND * 12; i += blockDim.x) sW[i] = W1[i];
    __syncthreads();
    int i = blockIdx.x * blockDim.x + threadIdx.x;
    if (i >= n) return;
    float acc[12];
    #pragma unroll
    for (int d = 0; d < 12; d++) acc[d] = 0.0f;
    const float4* xr = reinterpret_cast<const float4*>(X + (size_t)i * IND);
    #pragma unroll
    for (int k4 = 0; k4 < IND / 4; k4++) {
        float4 v = xr[k4];
        const float* w = &sW[k4 * 48];
        #pragma unroll
        for (int d = 0; d < 12; d++)
            acc[d] += v.x * w[d] + v.y * w[12 + d] + v.z * w[24 + d] + v.w * w[36 + d];
    }
    float di = g_dis[i];
    float4* hO = reinterpret_cast<float4*>(g_h    + (size_t)i * 12);
    float4* aO = reinterpret_cast<float4*>(g_accA + (size_t)i * 12);
    #pragma unroll
    for (int q = 0; q < 3; q++) {
        float4 hp = make_float4(di * acc[q*4+0], di * acc[q*4+1], di * acc[q*4+2], di * acc[q*4+3]);
        hO[q] = hp;
        aO[q] = hp;
    }
}

// ---------------- edge scatter kernels (4 edges / thread) ----------------
__device__ __forceinline__ void edge12(int s, int d, float w) {
    const float4* hs = reinterpret_cast<const float4*>(g_h + (size_t)s * 12);
    float4 h0 = hs[0], h1 = hs[1], h2 = hs[2];
    float* op = g_accA + (size_t)d * 12;
    red4(op + 0, w * h0.x, w * h0.y, w * h0.z, w * h0.w);
    red4(op + 4, w * h1.x, w * h1.y, w * h1.z, w * h1.w);
    red4(op + 8, w * h2.x, w * h2.y, w * h2.z, w * h2.w);
}
__global__ void __launch_bounds__(256) k_scat1(const float* __restrict__ ew, int E) {
    int e0 = (blockIdx.x * blockDim.x + threadIdx.x) * 4;
    if (e0 + 4 <= E) {
        int4   s4 = *reinterpret_cast<const int4*>(g_src + e0);
        int4   d4 = *reinterpret_cast<const int4*>(g_dst + e0);
        float4 w4 = *reinterpret_cast<const float4*>(ew + e0);
        edge12(s4.x, d4.x, w4.x);
        edge12(s4.y, d4.y, w4.y);
        edge12(s4.z, d4.z, w4.z);
        edge12(s4.w, d4.w, w4.w);
    } else {
        for (int e = e0; e < E; e++) edge12(g_src[e], g_dst[e], ew[e]);
    }
}

__device__ __forceinline__ void edge6(int s, int d, float w) {
    const float2* hs = reinterpret_cast<const float2*>(g_h + (size_t)s * 6);
    float2 h0 = hs[0], h1 = hs[1], h2 = hs[2];
    float* op = g_accB + (size_t)d * 6;
    red2(op + 0, w * h0.x, w * h0.y);
    red2(op + 2, w * h1.x, w * h1.y);
    red2(op + 4, w * h2.x, w * h2.y);
}
__global__ void __launch_bounds__(256) k_scat2(const float* __restrict__ ew, int E) {
    int e0 = (blockIdx.x * blockDim.x + threadIdx.x) * 4;
    if (e0 + 4 <= E) {
        int4   s4 = *reinterpret_cast<const int4*>(g_src + e0);
        int4   d4 = *reinterpret_cast<const int4*>(g_dst + e0);
        float4 w4 = *reinterpret_cast<const float4*>(ew + e0);
        edge6(s4.x, d4.x, w4.x);
        edge6(s4.y, d4.y, w4.y);
        edge6(s4.z, d4.z, w4.z);
        edge6(s4.w, d4.w, w4.w);
    } else {
        for (int e = e0; e < E; e++) edge6(g_src[e], g_dst[e], ew[e]);
    }
}

__device__ __forceinline__ void edge3(int s, int d, float w) {
    float4 h = *reinterpret_cast<const float4*>(g_h + (size_t)s * 4);
    red4(g_accA + (size_t)d * 4, w * h.x, w * h.y, w * h.z, 0.0f);
}
__global__ void __launch_bounds__(256) k_scat3(const float* __restrict__ ew, int E) {
    int e0 = (blockIdx.x * blockDim.x + threadIdx.x) * 4;
    if (e0 + 4 <= E) {
        int4   s4 = *reinterpret_cast<const int4*>(g_src + e0);
        int4   d4 = *reinterpret_cast<const int4*>(g_dst + e0);
        float4 w4 = *reinterpret_cast<const float4*>(ew + e0);
        edge3(s4.x, d4.x, w4.x);
        edge3(s4.y, d4.y, w4.y);
        edge3(s4.z, d4.z, w4.z);
        edge3(s4.w, d4.w, w4.w);
    } else {
        for (int e = e0; e < E; e++) edge3(g_src[e], g_dst[e], ew[e]);
    }
}

// ---------------- layer 2: x2 = relu(dis*accA + b1); h' = dis*(x2@W2); accB init = h' ----------------
__global__ void k_mm2(const float* __restrict__ W2, const float* __restrict__ b1, int n) {
    int i = blockIdx.x * blockDim.x + threadIdx.x;
    if (i >= n) return;
    float di = g_dis[i];
    const float4* a4 = reinterpret_cast<const float4*>(g_accA + (size_t)i * 12);
    float4 v0 = a4[0], v1 = a4[1], v2 = a4[2];
    float x[12] = {v0.x, v0.y, v0.z, v0.w, v1.x, v1.y, v1.z, v1.w, v2.x, v2.y, v2.z, v2.w};
    float acc[6];
    #pragma unroll
    for (int d = 0; d < 6; d++) acc[d] = 0.0f;
    #pragma unroll
    for (int k = 0; k < 12; k++) {
        float xv = fmaxf(fmaf(di, x[k], __ldg(&b1[k])), 0.0f);
        #pragma unroll
        for (int d = 0; d < 6; d++)
            acc[d] = fmaf(xv, __ldg(&W2[k * 6 + d]), acc[d]);
    }
    float2* hO = reinterpret_cast<float2*>(g_h    + (size_t)i * 6);
    float2* aO = reinterpret_cast<float2*>(g_accB + (size_t)i * 6);
    #pragma unroll
    for (int q = 0; q < 3; q++) {
        float2 hp = make_float2(di * acc[q*2+0], di * acc[q*2+1]);
        hO[q] = hp;
        aO[q] = hp;
    }
}

// ---------------- layer 3: x3 = relu(dis*accB + b2); h' = dis*(x3@W3) padded to 4; accA init ----------------
__global__ void k_mm3(const float* __restrict__ W3, const float* __restrict__ b2, int n) {
    int i = blockIdx.x * blockDim.x + threadIdx.x;
    if (i >= n) return;
    float di = g_dis[i];
    const float2* a2 = reinterpret_cast<const float2*>(g_accB + (size_t)i * 6);
    float2 u0 = a2[0], u1 = a2[1], u2 = a2[2];
    float x[6] = {u0.x, u0.y, u1.x, u1.y, u2.x, u2.y};
    float acc[3] = {0.0f, 0.0f, 0.0f};
    #pragma unroll
    for (int k = 0; k < 6; k++) {
        float xv = fmaxf(fmaf(di, x[k], __ldg(&b2[k])), 0.0f);
        #pragma unroll
        for (int d = 0; d < 3; d++)
            acc[d] = fmaf(xv, __ldg(&W3[k * 3 + d]), acc[d]);
    }
    float4 hp = make_float4(di * acc[0], di * acc[1], di * acc[2], 0.0f);
    *reinterpret_cast<float4*>(g_h    + (size_t)i * 4) = hp;
    *reinterpret_cast<float4*>(g_accA + (size_t)i * 4) = hp;
}

// ---------------- final: sigmoid(relu(dis*accA + b3) . Wl + bl) ----------------
__global__ void k_final(const float* __restrict__ b3, const float* __restrict__ Wl,
                        const float* __restrict__ bl, float* __restrict__ out, int n) {
    int i = blockIdx.x * blockDim.x + threadIdx.x;
    if (i >= n) return;
    float di = g_dis[i];
    float4 a = *reinterpret_cast<const float4*>(g_accA + (size_t)i * 4);
    float v0 = fmaxf(fmaf(di, a.x, __ldg(&b3[0])), 0.0f);
    float v1 = fmaxf(fmaf(di, a.y, __ldg(&b3[1])), 0.0f);
    float v2 = fmaxf(fmaf(di, a.z, __ldg(&b3[2])), 0.0f);
    float z = __ldg(&bl[0]);
    z = fmaf(v0, __ldg(&Wl[0]), z);
    z = fmaf(v1, __ldg(&Wl[1]), z);
    z = fmaf(v2, __ldg(&Wl[2]), z);
    out[i] = 1.0f / (1.0f + expf(-z));
}

// ---------------- launcher ----------------
extern "C" void kernel_launch(void* const* d_in, const int* in_sizes, int n_in,
                              void* d_out, int out_size) {
    const float* X  = (const float*)d_in[0];
    const void*  EI = d_in[1];
    const float* EW = (const float*)d_in[2];
    const float* W1 = (const float*)d_in[3];
    const float* B1 = (const float*)d_in[4];
    const float* W2 = (const float*)d_in[5];
    const float* B2 = (const float*)d_in[6];
    const float* W3 = (const float*)d_in[7];
    const float* B3 = (const float*)d_in[8];
    const float* WL = (const float*)d_in[9];
    const float* BL = (const float*)d_in[10];

    int n = in_sizes[0] / IND;
    if (n > NN) n = NN;
    int E = in_sizes[2];
    if (E > NE) E = NE;

    int nb  = (n + 255) / 256;
    int eb  = (E + 255) / 256;
    int eb4 = ((E + 3) / 4 + 255) / 256;

    k_detect<<<1, 32>>>((const unsigned int*)EI);
    k_init_deg<<<nb, 256>>>(n);
    k_deg_convert<<<eb, 256>>>(EI, EW, E);
    k_dis<<<nb, 256>>>(n);

    k_mm1<<<(n + 127) / 128, 128>>>(X, W1, n);
    k_scat1<<<eb4, 256>>>(EW, E);

    k_mm2<<<nb, 256>>>(W2, B1, n);
    k_scat2<<<eb4, 256>>>(EW, E);

    k_mm3<<<nb, 256>>>(W3, B2, n);
    k_scat3<<<eb4, 256>>>(EW, E);

    k_final<<<nb, 256>>>(B3, WL, BL, (float*)d_out, n);
}

// round 5
// speedup vs baseline: 1.4493x; 1.4493x over previous
#include <cuda_runtime.h>
#include <math.h>

#define NN  100000
#define NE  6400000
#define IND 128
#define NB1MAX 128   // max scan blocks (ceil(100000/1024)=98)

// ---------------- static device scratch (no runtime allocation) ----------------
static __device__ int   g_is64;
static __device__ int   g_cnt[NN];        // in-degree (edge count) per node
static __device__ int   g_rowstart[NN];   // exclusive prefix of g_cnt
static __device__ int   g_cursor[NN];     // placement tickets
static __device__ int   g_blksum[NB1MAX];
static __device__ int   g_blkoff[NB1MAX];
static __device__ float g_dis[NN];        // deg^{-1/2}
static __device__ __align__(16) float g_h1[NN * 16];  // layer-1 h' (12 used, 64B stride)
static __device__ __align__(16) float g_h2[NN * 8];   // layer-2 h' (6 used, 32B stride)
static __device__ __align__(16) float g_h3[NN * 4];   // layer-3 h' (3 used, 16B stride)
static __device__ __align__(16) int2  g_csr[NE];      // (src, weight-bits) grouped by dst

// ---------------- dtype detection: int64 edge_index has zero high words ----------------
__global__ void k_detect(const unsigned int* __restrict__ p) {
    if (threadIdx.x == 0 && blockIdx.x == 0) {
        int is64 = 1;
        #pragma unroll
        for (int j = 0; j < 16; j++)
            if (p[2 * j + 1] != 0u) is64 = 0;
        g_is64 = is64;
    }
}

__global__ void k_zero(int n) {
    int i = blockIdx.x * blockDim.x + threadIdx.x;
    if (i < n) g_cnt[i] = 0;
}

// count edges per destination (reads dst row of edge_index only)
__global__ void k_count(const void* __restrict__ eiv, int E) {
    int e = blockIdx.x * blockDim.x + threadIdx.x;
    if (e >= E) return;
    int d;
    if (g_is64) d = (int)((const long long*)eiv)[(long long)E + e];
    else        d = ((const int*)eiv)[E + e];
    atomicAdd(&g_cnt[d], 1);
}

// ---------------- 3-kernel exclusive scan of g_cnt -> g_rowstart ----------------
__global__ void k_scan1(int n) {
    __shared__ int ss[256];
    int tid = threadIdx.x;
    int base = blockIdx.x * 1024 + tid * 4;
    int c0 = (base + 0 < n) ? g_cnt[base + 0] : 0;
    int c1 = (base + 1 < n) ? g_cnt[base + 1] : 0;
    int c2 = (base + 2 < n) ? g_cnt[base + 2] : 0;
    int c3 = (base + 3 < n) ? g_cnt[base + 3] : 0;
    int s = c0 + c1 + c2 + c3;
    ss[tid] = s;
    __syncthreads();
    #pragma unroll
    for (int off = 1; off < 256; off <<= 1) {
        int v = (tid >= off) ? ss[tid - off] : 0;
        __syncthreads();
        ss[tid] += v;
        __syncthreads();
    }
    int excl = ss[tid] - s;
    if (tid == 255) g_blksum[blockIdx.x] = ss[255];
    int r = excl;
    if (base + 0 < n) g_rowstart[base + 0] = r; r += c0;
    if (base + 1 < n) g_rowstart[base + 1] = r; r += c1;
    if (base + 2 < n) g_rowstart[base + 2] = r; r += c2;
    if (base + 3 < n) g_rowstart[base + 3] = r;
}

__global__ void k_scan2(int nb1) {
    __shared__ int ss[128];
    int tid = threadIdx.x;
    int v = (tid < nb1) ? g_blksum[tid] : 0;
    ss[tid] = v;
    __syncthreads();
    #pragma unroll
    for (int off = 1; off < 128; off <<= 1) {
        int u = (tid >= off) ? ss[tid - off] : 0;
        __syncthreads();
        ss[tid] += u;
        __syncthreads();
    }
    if (tid < nb1) g_blkoff[tid] = ss[tid] - v;
}

__global__ void k_scan3(int n) {
    int i = blockIdx.x * blockDim.x + threadIdx.x;
    if (i >= n) return;
    int r = g_rowstart[i] + g_blkoff[i >> 10];
    g_rowstart[i] = r;
    g_cursor[i]   = r;
}

// ---------------- CSR placement: (src, w) grouped by dst ----------------
__global__ void k_place(const void* __restrict__ eiv, const float* __restrict__ ew, int E) {
    int e = blockIdx.x * blockDim.x + threadIdx.x;
    if (e >= E) return;
    int s, d;
    if (g_is64) {
        const long long* ei = (const long long*)eiv;
        s = (int)ei[e];
        d = (int)ei[(long long)E + e];
    } else {
        const int* ei = (const int*)eiv;
        s = ei[e];
        d = ei[E + e];
    }
    float w = ew[e];
    int pos = atomicAdd(&g_cursor[d], 1);
    g_csr[pos] = make_int2(s, __float_as_int(w));
}

// ---------------- warp shuffle reduce helper ----------------
__device__ __forceinline__ float wred(float v) {
    #pragma unroll
    for (int o = 16; o; o >>= 1) v += __shfl_down_sync(0xffffffffu, v, o);
    return v;
}

// ---------------- weighted degree -> dis = rsqrt(1 + sum w) ----------------
__global__ void __launch_bounds__(256) k_deg(int n) {
    int gid  = blockIdx.x * blockDim.x + threadIdx.x;
    int node = gid >> 5, lane = gid & 31;
    if (node >= n) return;
    int beg = g_rowstart[node], cnt = g_cnt[node];
    float s = 0.0f;
    for (int j = lane; j < cnt; j += 32)
        s += __int_as_float(g_csr[beg + j].y);
    s = wred(s);
    if (lane == 0) g_dis[node] = rsqrtf(1.0f + s);  // self-loop weight 1
}

// ---------------- layer 1 matmul: h1' = dis * (X @ W1), 64B row stride ----------------
__global__ void __launch_bounds__(128) k_mm1(const float* __restrict__ X,
                                             const float* __restrict__ W1, int n) {
    __shared__ float sW[IND * 12];
    for (int i = threadIdx.x; i < IND * 12; i += blockDim.x) sW[i] = W1[i];
    __syncthreads();
    int i = blockIdx.x * blockDim.x + threadIdx.x;
    if (i >= n) return;
    float acc[12];
    #pragma unroll
    for (int d = 0; d < 12; d++) acc[d] = 0.0f;
    const float4* xr = reinterpret_cast<const float4*>(X + (size_t)i * IND);
    #pragma unroll
    for (int k4 = 0; k4 < IND / 4; k4++) {
        float4 v = xr[k4];
        const float* w = &sW[k4 * 48];
        #pragma unroll
        for (int d = 0; d < 12; d++)
            acc[d] += v.x * w[d] + v.y * w[12 + d] + v.z * w[24 + d] + v.w * w[36 + d];
    }
    float di = g_dis[i];
    float4* hO = reinterpret_cast<float4*>(g_h1 + (size_t)i * 16);
    #pragma unroll
    for (int q = 0; q < 3; q++)
        hO[q] = make_float4(di * acc[q*4+0], di * acc[q*4+1], di * acc[q*4+2], di * acc[q*4+3]);
}

// ---------------- layer-1 gather (+ fused relu + mm2): warp per node ----------------
__global__ void __launch_bounds__(256) k_gat1(const float* __restrict__ b1,
                                              const float* __restrict__ W2, int n) {
    int gid  = blockIdx.x * blockDim.x + threadIdx.x;
    int node = gid >> 5, lane = gid & 31;
    if (node >= n) return;
    int beg = g_rowstart[node], cnt = g_cnt[node];
    float acc[12];
    #pragma unroll
    for (int d = 0; d < 12; d++) acc[d] = 0.0f;
    for (int j = lane; j < cnt; j += 32) {
        int2 e = g_csr[beg + j];
        float w = __int_as_float(e.y);
        const float4* hs = reinterpret_cast<const float4*>(g_h1 + (size_t)e.x * 16);
        float4 a = hs[0], b = hs[1], c = hs[2];
        acc[0] += w * a.x;  acc[1] += w * a.y;  acc[2]  += w * a.z;  acc[3]  += w * a.w;
        acc[4] += w * b.x;  acc[5] += w * b.y;  acc[6]  += w * b.z;  acc[7]  += w * b.w;
        acc[8] += w * c.x;  acc[9] += w * c.y;  acc[10] += w * c.z;  acc[11] += w * c.w;
    }
    #pragma unroll
    for (int d = 0; d < 12; d++) acc[d] = wred(acc[d]);
    if (lane == 0) {
        float di = g_dis[node];
        const float* self = g_h1 + (size_t)node * 16;
        float o[6];
        #pragma unroll
        for (int d = 0; d < 6; d++) o[d] = 0.0f;
        #pragma unroll
        for (int k = 0; k < 12; k++) {
            float xv = fmaxf(fmaf(di, acc[k] + self[k], __ldg(&b1[k])), 0.0f);
            #pragma unroll
            for (int d = 0; d < 6; d++)
                o[d] = fmaf(xv, __ldg(&W2[k * 6 + d]), o[d]);
        }
        float4* hO = reinterpret_cast<float4*>(g_h2 + (size_t)node * 8);
        hO[0] = make_float4(di * o[0], di * o[1], di * o[2], di * o[3]);
        hO[1] = make_float4(di * o[4], di * o[5], 0.0f, 0.0f);
    }
}

// ---------------- layer-2 gather (+ fused relu + mm3) ----------------
__global__ void __launch_bounds__(256) k_gat2(const float* __restrict__ b2,
                                              const float* __restrict__ W3, int n) {
    int gid  = blockIdx.x * blockDim.x + threadIdx.x;
    int node = gid >> 5, lane = gid & 31;
    if (node >= n) return;
    int beg = g_rowstart[node], cnt = g_cnt[node];
    float acc[6];
    #pragma unroll
    for (int d = 0; d < 6; d++) acc[d] = 0.0f;
    for (int j = lane; j < cnt; j += 32) {
        int2 e = g_csr[beg + j];
        float w = __int_as_float(e.y);
        const float4* hs = reinterpret_cast<const float4*>(g_h2 + (size_t)e.x * 8);
        float4 a = hs[0], b = hs[1];
        acc[0] += w * a.x;  acc[1] += w * a.y;  acc[2] += w * a.z;
        acc[3] += w * a.w;  acc[4] += w * b.x;  acc[5] += w * b.y;
    }
    #pragma unroll
    for (int d = 0; d < 6; d++) acc[d] = wred(acc[d]);
    if (lane == 0) {
        float di = g_dis[node];
        const float* self = g_h2 + (size_t)node * 8;
        float o[3] = {0.0f, 0.0f, 0.0f};
        #pragma unroll
        for (int k = 0; k < 6; k++) {
            float xv = fmaxf(fmaf(di, acc[k] + self[k], __ldg(&b2[k])), 0.0f);
            #pragma unroll
            for (int d = 0; d < 3; d++)
                o[d] = fmaf(xv, __ldg(&W3[k * 3 + d]), o[d]);
        }
        *reinterpret_cast<float4*>(g_h3 + (size_t)node * 4) =
            make_float4(di * o[0], di * o[1], di * o[2], 0.0f);
    }
}

// ---------------- layer-3 gather (+ fused relu + linear + sigmoid) ----------------
__global__ void __launch_bounds__(256) k_gat3(const float* __restrict__ b3,
                                              const float* __restrict__ Wl,
                                              const float* __restrict__ bl,
                                              float* __restrict__ out, int n) {
    int gid  = blockIdx.x * blockDim.x + threadIdx.x;
    int node = gid >> 5, lane = gid & 31;
    if (node >= n) return;
    int beg = g_rowstart[node], cnt = g_cnt[node];
    float a0 = 0.0f, a1 = 0.0f, a2 = 0.0f;
    for (int j = lane; j < cnt; j += 32) {
        int2 e = g_csr[beg + j];
        float w = __int_as_float(e.y);
        float4 h = *reinterpret_cast<const float4*>(g_h3 + (size_t)e.x * 4);
        a0 += w * h.x;  a1 += w * h.y;  a2 += w * h.z;
    }
    a0 = wred(a0);  a1 = wred(a1);  a2 = wred(a2);
    if (lane == 0) {
        float di = g_dis[node];
        const float* self = g_h3 + (size_t)node * 4;
        float v0 = fmaxf(fmaf(di, a0 + self[0], __ldg(&b3[0])), 0.0f);
        float v1 = fmaxf(fmaf(di, a1 + self[1], __ldg(&b3[1])), 0.0f);
        float v2 = fmaxf(fmaf(di, a2 + self[2], __ldg(&b3[2])), 0.0f);
        float z = __ldg(&bl[0]);
        z = fmaf(v0, __ldg(&Wl[0]), z);
        z = fmaf(v1, __ldg(&Wl[1]), z);
        z = fmaf(v2, __ldg(&Wl[2]), z);
        out[node] = 1.0f / (1.0f + expf(-z));
    }
}

// ---------------- launcher ----------------
extern "C" void kernel_launch(void* const* d_in, const int* in_sizes, int n_in,
                              void* d_out, int out_size) {
    const float* X  = (const float*)d_in[0];
    const void*  EI = d_in[1];
    const float* EW = (const float*)d_in[2];
    const float* W1 = (const float*)d_in[3];
    const float* B1 = (const float*)d_in[4];
    const float* W2 = (const float*)d_in[5];
    const float* B2 = (const float*)d_in[6];
    const float* W3 = (const float*)d_in[7];
    const float* B3 = (const float*)d_in[8];
    const float* WL = (const float*)d_in[9];
    const float* BL = (const float*)d_in[10];

    int n = in_sizes[0] / IND;
    if (n > NN) n = NN;
    int E = in_sizes[2];
    if (E > NE) E = NE;

    int nb   = (n + 255) / 256;
    int eb   = (E + 255) / 256;
    int nb1  = (n + 1023) / 1024;           // scan blocks
    int wb   = ((n * 32) + 255) / 256;      // warp-per-node blocks

    k_detect<<<1, 32>>>((const unsigned int*)EI);
    k_zero  <<<nb, 256>>>(n);
    k_count <<<eb, 256>>>(EI, E);
    k_scan1 <<<nb1, 256>>>(n);
    k_scan2 <<<1, 128>>>(nb1);
    k_scan3 <<<nb, 256>>>(n);
    k_place <<<eb, 256>>>(EI, EW, E);

    k_deg   <<<wb, 256>>>(n);
    k_mm1   <<<(n + 127) / 128, 128>>>(X, W1, n);
    k_gat1  <<<wb, 256>>>(B1, W2, n);
    k_gat2  <<<wb, 256>>>(B2, W3, n);
    k_gat3  <<<wb, 256>>>(B3, WL, BL, (float*)d_out, n);
}